// round 16
// baseline (speedup 1.0000x reference)
#include <cuda_runtime.h>
#include <math.h>

#define N_NODES 500000
#define N_EDGES 32000000

// Per-node packed contribution: u32 = [cos16 | sin16], x16 = round(16384*x)+16384.
__device__ unsigned int g_enc[N_NODES];
// Integer accumulator: [cnt @bit52 | sum cos16 : 26b | sum sin16 : 26b] (exact)
__device__ unsigned long long g_acc[N_NODES];

__device__ __forceinline__ void red_add_u64(unsigned long long* p, unsigned long long v) {
    asm volatile("red.global.add.u64 [%0], %1;" :: "l"(p), "l"(v) : "memory");
}

// Random gather with sticky-L1 policy: table lines persist, raising hit rate.
__device__ __forceinline__ unsigned int ldg_sticky(const unsigned int* p) {
    unsigned int v;
    asm volatile("ld.global.nc.L1::evict_last.u32 %0, [%1];" : "=r"(v) : "l"(p));
    return v;
}
// Streaming index load: don't pollute L1 (single-use data).
__device__ __forceinline__ int4 ldg_stream(const int4* p) {
    int4 v;
    asm volatile("ld.global.nc.L1::evict_first.v4.u32 {%0,%1,%2,%3}, [%4];"
                 : "=r"(v.x), "=r"(v.y), "=r"(v.z), "=r"(v.w) : "l"(p));
    return v;
}

// Prologue: zero accumulators + pack sin/cos of theta into u32
__global__ void prologue_kernel(const float* __restrict__ theta) {
    int i = blockIdx.x * blockDim.x + threadIdx.x;
    if (i < N_NODES) {
        g_acc[i] = 0ULL;
        float t = theta[i];
        unsigned int si = (unsigned int)(lrintf(__sinf(t) * 16384.0f) + 16384);
        unsigned int ci = (unsigned int)(lrintf(__cosf(t) * 16384.0f) + 16384);
        g_enc[i] = (ci << 16) | si;
    }
    cudaTriggerProgrammaticLaunchCompletion();
}

// Expand packed u32 to the u64 RED operand: cnt=1 @52, cos field @26, sin field @0.
__device__ __forceinline__ unsigned long long expand(unsigned int e) {
    return (1ULL << 52) | ((unsigned long long)(e >> 16) << 26)
                        | (unsigned long long)(e & 0xFFFFu);
}

// Edge kernel: 4 edges/thread, 512-thread CTAs. Per edge: one 4B random gather
// (sticky L1) + one u64 RED. Bound by LTS gather+atomic slot rate (~238us wall).
__global__ void __launch_bounds__(512) edge_kernel(const int4* __restrict__ src4,
                                                   const int4* __restrict__ dst4) {
    int i = blockIdx.x * blockDim.x + threadIdx.x;

    // Independent prefix (before PDL wait): stream indices, L1-transient
    int4 s = ldg_stream(&src4[i]);
    int4 d = ldg_stream(&dst4[i]);

    cudaGridDependencySynchronize();  // g_enc / g_acc ready

    unsigned int e0 = ldg_sticky(&g_enc[s.x]);
    unsigned int e1 = ldg_sticky(&g_enc[s.y]);
    red_add_u64(&g_acc[d.x], expand(e0));
    unsigned int e2 = ldg_sticky(&g_enc[s.z]);
    red_add_u64(&g_acc[d.y], expand(e1));
    unsigned int e3 = ldg_sticky(&g_enc[s.w]);
    red_add_u64(&g_acc[d.z], expand(e2));
    red_add_u64(&g_acc[d.w], expand(e3));

    cudaTriggerProgrammaticLaunchCompletion();
}

// Epilogue: decode fields, w = c*(cos*Ssin - sin*Scos)/max(cnt,1); v = u0*[cos,sin]
__global__ void __launch_bounds__(512) node_kernel(const float* __restrict__ theta,
                            const float* __restrict__ logc,
                            const float* __restrict__ u0p,
                            float* __restrict__ out) {
    int i = blockIdx.x * blockDim.x + threadIdx.x;
    if (i >= N_NODES) {
        cudaGridDependencySynchronize();
        return;
    }
    // Independent prefix
    float c = __expf(*logc);
    float u0 = *u0p;
    float t = theta[i];
    float sn = __sinf(t);
    float cs = __cosf(t);

    cudaGridDependencySynchronize();  // edge atomics complete

    unsigned long long a = g_acc[i];
    long long cnt    = (long long)(a >> 52);
    long long sfield = (long long)(a & 0x3FFFFFFULL);
    long long cfield = (long long)((a >> 26) & 0x3FFFFFFULL);
    // exact integer de-bias (bias 16384 per contribution), then scale by 1/16384
    float Ssin = (float)(sfield - 16384LL * cnt) * (1.0f / 16384.0f);
    float Scos = (float)(cfield - 16384LL * cnt) * (1.0f / 16384.0f);

    float denom = fmaxf((float)cnt, 1.0f);
    float w = c * (cs * Ssin - sn * Scos) / denom;

    out[3 * i + 0] = w;
    out[3 * i + 1] = u0 * cs;
    out[3 * i + 2] = u0 * sn;
}

extern "C" void kernel_launch(void* const* d_in, const int* in_sizes, int n_in,
                              void* d_out, int out_size) {
    // Input order (setup_inputs): theta, logc, u0, src, dst
    const float* theta = (const float*)d_in[0];
    const float* logc  = (const float*)d_in[1];
    const float* u0    = (const float*)d_in[2];
    const int*   src   = (const int*)d_in[3];
    const int*   dst   = (const int*)d_in[4];
    float* out = (float*)d_out;

    const int nquads = N_EDGES / 4;  // 8M, exactly 15625 blocks of 512

    // Launch 1: prologue
    {
        int threads = 256;
        int blocks = (N_NODES + threads - 1) / threads;
        prologue_kernel<<<blocks, threads>>>(theta);
    }
    // Launch 2: edge kernel (PDL)
    {
        cudaLaunchConfig_t cfg = {};
        cfg.blockDim = dim3(512, 1, 1);
        cfg.gridDim = dim3(nquads / 512, 1, 1);
        cudaLaunchAttribute attr[1];
        attr[0].id = cudaLaunchAttributeProgrammaticStreamSerialization;
        attr[0].val.programmaticStreamSerializationAllowed = 1;
        cfg.attrs = attr;
        cfg.numAttrs = 1;
        cudaLaunchKernelEx(&cfg, edge_kernel, (const int4*)src, (const int4*)dst);
    }
    // Launch 3: epilogue (PDL)
    {
        cudaLaunchConfig_t cfg = {};
        cfg.blockDim = dim3(512, 1, 1);
        cfg.gridDim = dim3((N_NODES + 511) / 512, 1, 1);
        cudaLaunchAttribute attr[1];
        attr[0].id = cudaLaunchAttributeProgrammaticStreamSerialization;
        attr[0].val.programmaticStreamSerializationAllowed = 1;
        cfg.attrs = attr;
        cfg.numAttrs = 1;
        cudaLaunchKernelEx(&cfg, node_kernel, theta, logc, u0, out);
    }
}

// round 17
// speedup vs baseline: 1.0079x; 1.0079x over previous
#include <cuda_runtime.h>
#include <math.h>

#define N_NODES 500000
#define N_EDGES 32000000

// Per-node packed contribution: u32 = [cos16 | sin16], x16 = round(16384*x)+16384.
__device__ unsigned int g_enc[N_NODES];
// Integer accumulator: [cnt @bit52 | sum cos16 : 26b | sum sin16 : 26b] (exact)
__device__ unsigned long long g_acc[N_NODES];

__device__ __forceinline__ void red_add_u64(unsigned long long* p, unsigned long long v) {
    asm volatile("red.global.add.u64 [%0], %1;" :: "l"(p), "l"(v) : "memory");
}

// Prologue: zero accumulators + pack sin/cos of theta into u32
__global__ void prologue_kernel(const float* __restrict__ theta) {
    int i = blockIdx.x * blockDim.x + threadIdx.x;
    if (i < N_NODES) {
        g_acc[i] = 0ULL;
        float t = theta[i];
        unsigned int si = (unsigned int)(lrintf(__sinf(t) * 16384.0f) + 16384);
        unsigned int ci = (unsigned int)(lrintf(__cosf(t) * 16384.0f) + 16384);
        g_enc[i] = (ci << 16) | si;
    }
    cudaTriggerProgrammaticLaunchCompletion();
}

// Expand packed u32 to the u64 RED operand: cnt=1 @52, cos field @26, sin field @0.
__device__ __forceinline__ unsigned long long expand(unsigned int e) {
    return (1ULL << 52) | ((unsigned long long)(e >> 16) << 26)
                        | (unsigned long long)(e & 0xFFFFu);
}

// Edge kernel: 4 edges/thread, 512-thread CTAs. Per edge: one 4B random gather
// + one u64 RED. Bound by LTS gather+atomic slot rate — structural wall (~238us).
__global__ void __launch_bounds__(512) edge_kernel(const int4* __restrict__ src4,
                                                   const int4* __restrict__ dst4) {
    int i = blockIdx.x * blockDim.x + threadIdx.x;

    // Independent prefix (before PDL wait): stream indices
    int4 s = src4[i];
    int4 d = dst4[i];

    cudaGridDependencySynchronize();  // g_enc / g_acc ready

    unsigned int e0 = __ldg(&g_enc[s.x]);
    unsigned int e1 = __ldg(&g_enc[s.y]);
    red_add_u64(&g_acc[d.x], expand(e0));
    unsigned int e2 = __ldg(&g_enc[s.z]);
    red_add_u64(&g_acc[d.y], expand(e1));
    unsigned int e3 = __ldg(&g_enc[s.w]);
    red_add_u64(&g_acc[d.z], expand(e2));
    red_add_u64(&g_acc[d.w], expand(e3));

    cudaTriggerProgrammaticLaunchCompletion();
}

// Epilogue: decode fields, w = c*(cos*Ssin - sin*Scos)/max(cnt,1); v = u0*[cos,sin]
__global__ void __launch_bounds__(512) node_kernel(const float* __restrict__ theta,
                            const float* __restrict__ logc,
                            const float* __restrict__ u0p,
                            float* __restrict__ out) {
    int i = blockIdx.x * blockDim.x + threadIdx.x;
    if (i >= N_NODES) {
        cudaGridDependencySynchronize();
        return;
    }
    // Independent prefix
    float c = __expf(*logc);
    float u0 = *u0p;
    float t = theta[i];
    float sn = __sinf(t);
    float cs = __cosf(t);

    cudaGridDependencySynchronize();  // edge atomics complete

    unsigned long long a = g_acc[i];
    long long cnt    = (long long)(a >> 52);
    long long sfield = (long long)(a & 0x3FFFFFFULL);
    long long cfield = (long long)((a >> 26) & 0x3FFFFFFULL);
    // exact integer de-bias (bias 16384 per contribution), then scale by 1/16384
    float Ssin = (float)(sfield - 16384LL * cnt) * (1.0f / 16384.0f);
    float Scos = (float)(cfield - 16384LL * cnt) * (1.0f / 16384.0f);

    float denom = fmaxf((float)cnt, 1.0f);
    float w = c * (cs * Ssin - sn * Scos) / denom;

    out[3 * i + 0] = w;
    out[3 * i + 1] = u0 * cs;
    out[3 * i + 2] = u0 * sn;
}

extern "C" void kernel_launch(void* const* d_in, const int* in_sizes, int n_in,
                              void* d_out, int out_size) {
    // Input order (setup_inputs): theta, logc, u0, src, dst
    const float* theta = (const float*)d_in[0];
    const float* logc  = (const float*)d_in[1];
    const float* u0    = (const float*)d_in[2];
    const int*   src   = (const int*)d_in[3];
    const int*   dst   = (const int*)d_in[4];
    float* out = (float*)d_out;

    const int nquads = N_EDGES / 4;  // 8M, exactly 15625 blocks of 512

    // Launch 1: prologue
    {
        int threads = 256;
        int blocks = (N_NODES + threads - 1) / threads;
        prologue_kernel<<<blocks, threads>>>(theta);
    }
    // Launch 2: edge kernel (PDL)
    {
        cudaLaunchConfig_t cfg = {};
        cfg.blockDim = dim3(512, 1, 1);
        cfg.gridDim = dim3(nquads / 512, 1, 1);
        cudaLaunchAttribute attr[1];
        attr[0].id = cudaLaunchAttributeProgrammaticStreamSerialization;
        attr[0].val.programmaticStreamSerializationAllowed = 1;
        cfg.attrs = attr;
        cfg.numAttrs = 1;
        cudaLaunchKernelEx(&cfg, edge_kernel, (const int4*)src, (const int4*)dst);
    }
    // Launch 3: epilogue (PDL)
    {
        cudaLaunchConfig_t cfg = {};
        cfg.blockDim = dim3(512, 1, 1);
        cfg.gridDim = dim3((N_NODES + 511) / 512, 1, 1);
        cudaLaunchAttribute attr[1];
        attr[0].id = cudaLaunchAttributeProgrammaticStreamSerialization;
        attr[0].val.programmaticStreamSerializationAllowed = 1;
        cfg.attrs = attr;
        cfg.numAttrs = 1;
        cudaLaunchKernelEx(&cfg, node_kernel, theta, logc, u0, out);
    }
}